// round 5
// baseline (speedup 1.0000x reference)
#include <cuda_runtime.h>
#include <math.h>

#define B_       16
#define H_       16
#define D_       128
#define MAXS     2048
#define CHUNK_T  32            // tokens per CTA (2 cache blocks)
#define MAXCHUNK 64            // ceil(2047/32)
#define NTHREAD  256           // 8 warps x 2 heads = 16 heads
#define SCALE    0.08838834764831845f

// Partial scratch (allocation-free __device__ globals)
__device__ float g_po[B_ * H_ * MAXCHUNK * D_];   // 8 MB partial outputs
__device__ float g_pm[B_ * H_ * MAXCHUNK];
__device__ float g_pl[B_ * H_ * MAXCHUNK];
__device__ unsigned int g_cnt[B_ * H_];           // zero-init; reset by combiner

// RoPE a 128-float row for this lane's 4 columns (llama half-dim convention).
__device__ __forceinline__ float4 rope_row4(const float* __restrict__ row,
                                            const float* __restrict__ ctab,
                                            const float* __restrict__ stab,
                                            int lane)
{
    const int col = lane * 4;
    const float4 x  = *reinterpret_cast<const float4*>(row + col);
    const float4 xr = *reinterpret_cast<const float4*>(row + ((col + 64) & 127));
    const float  sg = (col < 64) ? -1.f : 1.f;
    const float4 c  = *reinterpret_cast<const float4*>(ctab + col);
    const float4 s  = *reinterpret_cast<const float4*>(stab + col);
    float4 r;
    r.x = x.x * c.x + sg * xr.x * s.x;
    r.y = x.y * c.y + sg * xr.y * s.y;
    r.z = x.z * c.z + sg * xr.z * s.z;
    r.w = x.w * c.w + sg * xr.w * s.w;
    return r;
}

__device__ __forceinline__ void upd(float& m, float& l, float4& acc,
                                    float sc, const float4& v4)
{
    const float mn   = fmaxf(m, sc);
    const float corr = __expf(m - mn);
    const float p    = __expf(sc - mn);
    l = l * corr + p;
    acc.x = acc.x * corr + p * v4.x;
    acc.y = acc.y * corr + p * v4.y;
    acc.z = acc.z * corr + p * v4.z;
    acc.w = acc.w * corr + p * v4.w;
    m = mn;
}

__global__ __launch_bounds__(NTHREAD) void paged_attn_chunk(
    const float* __restrict__ Q,            // [B,H,D]
    const float* __restrict__ K,
    const float* __restrict__ V,
    const float* __restrict__ Kc,           // [flat_slot,H,D]
    const float* __restrict__ Vc,
    const float* __restrict__ cosT,         // [MAXS,1,D]
    const float* __restrict__ sinT,
    const float* __restrict__ mask,         // [B,MAXS]
    const int*   __restrict__ cache_length, // [B]
    const int*   __restrict__ fetch_slots,  // [B,128]
    float*       __restrict__ out)          // [B,H,D]
{
    const int c    = blockIdx.x;            // chunk index
    const int b    = blockIdx.y;
    const int tid  = threadIdx.x;
    const int w    = tid >> 5;
    const int lane = tid & 31;
    const int h0   = 2 * w;
    const int h1   = 2 * w + 1;

    const int newpos = cache_length[b];
    const int L      = newpos + 1;
    const int s0     = c * CHUNK_T;
    if (s0 >= L) return;

    const int nact = (L + CHUNK_T - 1) / CHUNK_T;
    const int lim  = min(CHUNK_T, L - s0);         // valid positions this chunk
    const int limc = min(lim, newpos - s0);        // cached positions (< newpos)

    __shared__ __align__(16) float sh_mask[CHUNK_T];
    __shared__ int sh_fs[CHUNK_T / 16];

    if (tid < lim) sh_mask[tid] = mask[(size_t)b * MAXS + s0 + tid];
    if (tid < CHUNK_T / 16) sh_fs[tid] = fetch_slots[b * 128 + (s0 >> 4) + tid];
    __syncthreads();

    // Per-warp prologue: RoPE'd Q for both heads (registers only).
    const float* ctab = cosT + (size_t)newpos * D_;
    const float* stab = sinT + (size_t)newpos * D_;
    const float4 qa = rope_row4(Q + ((size_t)b * H_ + h0) * D_, ctab, stab, lane);
    const float4 qb = rope_row4(Q + ((size_t)b * H_ + h1) * D_, ctab, stab, lane);

    float  m0 = -1e30f, l0 = 0.f, m1 = -1e30f, l1 = 0.f;
    float4 a0 = make_float4(0.f, 0.f, 0.f, 0.f);
    float4 a1 = make_float4(0.f, 0.f, 0.f, 0.f);

    // Hot loop: one position per iter, both heads (adjacent 512B rows -> 1KB
    // contiguous per K / per V access; whole CTA stays in a 512KB window).
    for (int p = 0; p < limc; p++) {
        const int slot = sh_fs[p >> 4] * 16 + (p & 15);
        const float* kb = Kc + ((size_t)slot * H_ + h0) * D_;
        const float* vb = Vc + ((size_t)slot * H_ + h0) * D_;
        const float4 k0 = __ldcs(reinterpret_cast<const float4*>(kb) + lane);
        const float4 k1 = __ldcs(reinterpret_cast<const float4*>(kb + D_) + lane);
        const float4 v0 = __ldcs(reinterpret_cast<const float4*>(vb) + lane);
        const float4 v1 = __ldcs(reinterpret_cast<const float4*>(vb + D_) + lane);

        float d0 = qa.x * k0.x + qa.y * k0.y + qa.z * k0.z + qa.w * k0.w;
        float d1 = qb.x * k1.x + qb.y * k1.y + qb.z * k1.z + qb.w * k1.w;
        #pragma unroll
        for (int o = 16; o; o >>= 1) {
            d0 += __shfl_xor_sync(0xffffffffu, d0, o);
            d1 += __shfl_xor_sync(0xffffffffu, d1, o);
        }
        const float mk = sh_mask[p];
        upd(m0, l0, a0, d0 * SCALE + mk, v0);   // independent chains -> ILP
        upd(m1, l1, a1, d1 * SCALE + mk, v1);
    }

    // New token (always the last valid position overall) if it's in this chunk.
    if (limc < lim) {
        const float4 k0 = rope_row4(K + ((size_t)b * H_ + h0) * D_, ctab, stab, lane);
        const float4 k1 = rope_row4(K + ((size_t)b * H_ + h1) * D_, ctab, stab, lane);
        const float4 v0 = *(reinterpret_cast<const float4*>(V + ((size_t)b * H_ + h0) * D_) + lane);
        const float4 v1 = *(reinterpret_cast<const float4*>(V + ((size_t)b * H_ + h1) * D_) + lane);
        float d0 = qa.x * k0.x + qa.y * k0.y + qa.z * k0.z + qa.w * k0.w;
        float d1 = qb.x * k1.x + qb.y * k1.y + qb.z * k1.z + qb.w * k1.w;
        #pragma unroll
        for (int o = 16; o; o >>= 1) {
            d0 += __shfl_xor_sync(0xffffffffu, d0, o);
            d1 += __shfl_xor_sync(0xffffffffu, d1, o);
        }
        const float mk = sh_mask[newpos - s0];
        upd(m0, l0, a0, d0 * SCALE + mk, v0);
        upd(m1, l1, a1, d1 * SCALE + mk, v1);
    }

    // Write this chunk's partials (warp-private; no intra-CTA merge needed).
    const int p0 = (b * H_ + h0) * MAXCHUNK + c;
    const int p1 = (b * H_ + h1) * MAXCHUNK + c;
    *(reinterpret_cast<float4*>(g_po + (size_t)p0 * D_) + lane) = a0;
    *(reinterpret_cast<float4*>(g_po + (size_t)p1 * D_) + lane) = a1;
    if (lane == 0) { g_pm[p0] = m0; g_pl[p0] = l0; g_pm[p1] = m1; g_pl[p1] = l1; }
    __threadfence();

    // Per-head arrival; last-arriving warp combines that head.
    unsigned r0 = 0, r1 = 0;
    if (lane == 0) {
        r0 = atomicAdd(&g_cnt[b * H_ + h0], 1u);
        r1 = atomicAdd(&g_cnt[b * H_ + h1], 1u);
    }
    r0 = __shfl_sync(0xffffffffu, r0, 0);
    r1 = __shfl_sync(0xffffffffu, r1, 0);

    #pragma unroll
    for (int which = 0; which < 2; which++) {
        const unsigned r = which ? r1 : r0;
        const int      h = which ? h1 : h0;
        if (r == (unsigned)(nact - 1)) {
            __threadfence();
            const int base = (b * H_ + h) * MAXCHUNK;
            float M = -1e30f;
            for (int i = 0; i < nact; i++) M = fmaxf(M, g_pm[base + i]);
            float denom = 0.f;
            float4 od = make_float4(0.f, 0.f, 0.f, 0.f);
            #pragma unroll 4
            for (int i = 0; i < nact; i++) {
                const float e = __expf(g_pm[base + i] - M);
                denom += e * g_pl[base + i];
                const float4 t = *(reinterpret_cast<const float4*>(g_po + (size_t)(base + i) * D_) + lane);
                od.x += e * t.x; od.y += e * t.y; od.z += e * t.z; od.w += e * t.w;
            }
            const float inv = 1.f / denom;
            float4 o4;
            o4.x = od.x * inv; o4.y = od.y * inv; o4.z = od.z * inv; o4.w = od.w * inv;
            *(reinterpret_cast<float4*>(out + ((size_t)b * H_ + h) * D_) + lane) = o4;
            if (lane == 0) g_cnt[b * H_ + h] = 0;   // reset for next replay
        }
    }
}

// Inputs (metadata order):
//  0 Q  1 K  2 V  3 Kcache  4 Vcache  5 cos  6 sin  7 mask
//  8 input_length  9 cache_length  10 save_slots  11 fetch_slots  12 max_s
extern "C" void kernel_launch(void* const* d_in, const int* in_sizes, int n_in,
                              void* d_out, int out_size)
{
    const float* Q    = (const float*)d_in[0];
    const float* K    = (const float*)d_in[1];
    const float* V    = (const float*)d_in[2];
    const float* Kc   = (const float*)d_in[3];
    const float* Vc   = (const float*)d_in[4];
    const float* cosT = (const float*)d_in[5];
    const float* sinT = (const float*)d_in[6];
    const float* mask = (const float*)d_in[7];
    const int*   clen = (const int*)d_in[9];
    const int*   fsl  = (const int*)d_in[11];
    float* out = (float*)d_out;

    dim3 grid(MAXCHUNK, B_);
    paged_attn_chunk<<<grid, NTHREAD>>>(Q, K, V, Kc, Vc, cosT, sinT, mask, clen, fsl, out);
}

// round 6
// speedup vs baseline: 1.2650x; 1.2650x over previous
#include <cuda_runtime.h>
#include <math.h>

#define B_      16
#define H_      16
#define D_      128
#define MAXS    2048
#define NSPLIT  8
#define NWARP   8
#define NTHREAD 256
#define CHUNKMAX 256    // ceil(2047/8) = 256
#define SCALE   0.08838834764831845f

// Split-KV partial scratch (allocation-free: __device__ globals)
__device__ float g_po[B_ * H_ * NSPLIT * D_];
__device__ float g_pm[B_ * H_ * NSPLIT];
__device__ float g_pl[B_ * H_ * NSPLIT];
__device__ unsigned int g_cnt[B_ * H_];   // zero-init; reset by last CTA each call

__device__ __forceinline__ float dot4(const float4& a, const float4& b) {
    return a.x * b.x + a.y * b.y + a.z * b.z + a.w * b.w;
}

__global__ __launch_bounds__(NTHREAD) void paged_attn_fused(
    const float* __restrict__ Q,
    const float* __restrict__ K,
    const float* __restrict__ V,
    const float* __restrict__ Kc,           // [flat_slot,H,D]
    const float* __restrict__ Vc,
    const float* __restrict__ cosT,         // [MAXS,1,D]
    const float* __restrict__ sinT,
    const float* __restrict__ mask,         // [B,MAXS]
    const int*   __restrict__ cache_length, // [B]
    const int*   __restrict__ fetch_slots,  // [B,128]
    float*       __restrict__ out)          // [B,H,D]
{
    const int split = blockIdx.x;
    const int h     = blockIdx.y;
    const int b     = blockIdx.z;
    const int tid   = threadIdx.x;
    const int w     = tid >> 5;
    const int lane  = tid & 31;

    const int newpos = cache_length[b];
    const int L      = newpos + 1;
    const int bh     = b * H_ + h;
    const int pbase  = bh * NSPLIT;

    const int chunk = (L + NSPLIT - 1) / NSPLIT;
    const int s0    = split * chunk;
    const int nact  = min(NSPLIT, (L + chunk - 1) / chunk);

    __shared__ __align__(16) float sh_q[D_];
    __shared__ __align__(16) float sh_k[D_];
    __shared__ __align__(16) float sh_v[D_];
    __shared__ __align__(16) float sh_acc[NWARP][D_];
    __shared__ __align__(16) float sh_mask[CHUNKMAX];
    __shared__ float sh_m[NWARP];
    __shared__ float sh_l[NWARP];
    __shared__ int   sh_fs[CHUNKMAX / 16 + 2];
    __shared__ unsigned int sh_rank;

    const bool active = (s0 < L);

    if (active) {
        const int s1  = min(s0 + chunk, L);
        const int len = s1 - s0;
        const int f0  = s0 >> 4;
        const int nfs = ((s1 - 1) >> 4) - f0 + 1;

        if (tid < D_) {
            const float c  = cosT[(size_t)newpos * D_ + tid];
            const float sn = sinT[(size_t)newpos * D_ + tid];
            const float* qrow = Q + (size_t)bh * D_;
            const float* krow = K + (size_t)bh * D_;
            const float qrot = (tid < 64) ? -qrow[tid + 64] : qrow[tid - 64];
            const float krot = (tid < 64) ? -krow[tid + 64] : krow[tid - 64];
            sh_q[tid] = qrow[tid] * c + qrot * sn;
            sh_k[tid] = krow[tid] * c + krot * sn;
            sh_v[tid] = V[(size_t)bh * D_ + tid];
        }
        for (int i = tid; i < len; i += NTHREAD)
            sh_mask[i] = mask[(size_t)b * MAXS + s0 + i];
        if (tid < nfs)
            sh_fs[tid] = fetch_slots[b * 128 + f0 + tid];
        __syncthreads();

        const float4 q4 = reinterpret_cast<const float4*>(sh_q)[lane];

        float  m = -1e30f, l = 0.f;
        float4 acc = make_float4(0.f, 0.f, 0.f, 0.f);

        const int send = min(s1, newpos);
        int s = s0 + w;

        // 4-way unrolled mainloop: 8 LDG.128 in flight per warp (4 KB),
        // then one fused 4-element online-softmax update (5 MUFUs / 4 pos).
        for (; s + 3 * NWARP < send; s += 4 * NWARP) {
            const int sA = s, sB = s + NWARP, sC = s + 2 * NWARP, sD = s + 3 * NWARP;
            const int slA = sh_fs[(sA >> 4) - f0] * 16 + (sA & 15);
            const int slB = sh_fs[(sB >> 4) - f0] * 16 + (sB & 15);
            const int slC = sh_fs[(sC >> 4) - f0] * 16 + (sC & 15);
            const int slD = sh_fs[(sD >> 4) - f0] * 16 + (sD & 15);

            const float4 kA = __ldcs(reinterpret_cast<const float4*>(Kc + ((size_t)slA * H_ + h) * D_) + lane);
            const float4 kB = __ldcs(reinterpret_cast<const float4*>(Kc + ((size_t)slB * H_ + h) * D_) + lane);
            const float4 kC = __ldcs(reinterpret_cast<const float4*>(Kc + ((size_t)slC * H_ + h) * D_) + lane);
            const float4 kD = __ldcs(reinterpret_cast<const float4*>(Kc + ((size_t)slD * H_ + h) * D_) + lane);
            const float4 vA = __ldcs(reinterpret_cast<const float4*>(Vc + ((size_t)slA * H_ + h) * D_) + lane);
            const float4 vB = __ldcs(reinterpret_cast<const float4*>(Vc + ((size_t)slB * H_ + h) * D_) + lane);
            const float4 vC = __ldcs(reinterpret_cast<const float4*>(Vc + ((size_t)slC * H_ + h) * D_) + lane);
            const float4 vD = __ldcs(reinterpret_cast<const float4*>(Vc + ((size_t)slD * H_ + h) * D_) + lane);

            float dA = dot4(q4, kA), dB = dot4(q4, kB);
            float dC = dot4(q4, kC), dD = dot4(q4, kD);
            #pragma unroll
            for (int o = 16; o; o >>= 1) {
                dA += __shfl_xor_sync(0xffffffffu, dA, o);
                dB += __shfl_xor_sync(0xffffffffu, dB, o);
                dC += __shfl_xor_sync(0xffffffffu, dC, o);
                dD += __shfl_xor_sync(0xffffffffu, dD, o);
            }
            const float scA = dA * SCALE + sh_mask[sA - s0];
            const float scB = dB * SCALE + sh_mask[sB - s0];
            const float scC = dC * SCALE + sh_mask[sC - s0];
            const float scD = dD * SCALE + sh_mask[sD - s0];

            const float mn = fmaxf(fmaxf(m, fmaxf(scA, scB)), fmaxf(scC, scD));
            const float corr = __expf(m - mn);
            const float pA = __expf(scA - mn);
            const float pB = __expf(scB - mn);
            const float pC = __expf(scC - mn);
            const float pD = __expf(scD - mn);
            l = l * corr + (pA + pB) + (pC + pD);
            acc.x = acc.x * corr + pA * vA.x + pB * vB.x + pC * vC.x + pD * vD.x;
            acc.y = acc.y * corr + pA * vA.y + pB * vB.y + pC * vC.y + pD * vD.y;
            acc.z = acc.z * corr + pA * vA.z + pB * vB.z + pC * vC.z + pD * vD.z;
            acc.w = acc.w * corr + pA * vA.w + pB * vB.w + pC * vC.w + pD * vD.w;
            m = mn;
        }
        // Tail: up to 3 singles.
        for (; s < send; s += NWARP) {
            const int slot = sh_fs[(s >> 4) - f0] * 16 + (s & 15);
            const float4 k4 = __ldcs(reinterpret_cast<const float4*>(Kc + ((size_t)slot * H_ + h) * D_) + lane);
            const float4 v4 = __ldcs(reinterpret_cast<const float4*>(Vc + ((size_t)slot * H_ + h) * D_) + lane);
            float dot = dot4(q4, k4);
            #pragma unroll
            for (int o = 16; o; o >>= 1) dot += __shfl_xor_sync(0xffffffffu, dot, o);
            const float sc = dot * SCALE + sh_mask[s - s0];
            const float mn   = fmaxf(m, sc);
            const float corr = __expf(m - mn);
            const float p    = __expf(sc - mn);
            l = l * corr + p;
            acc.x = acc.x * corr + p * v4.x;
            acc.y = acc.y * corr + p * v4.y;
            acc.z = acc.z * corr + p * v4.z;
            acc.w = acc.w * corr + p * v4.w;
            m = mn;
        }

        // New token: warp 0 of the owning split.
        if (w == 0 && newpos >= s0 && newpos < s1) {
            const float4 k4 = reinterpret_cast<const float4*>(sh_k)[lane];
            const float4 v4 = reinterpret_cast<const float4*>(sh_v)[lane];
            float dot = dot4(q4, k4);
            #pragma unroll
            for (int o = 16; o; o >>= 1) dot += __shfl_xor_sync(0xffffffffu, dot, o);
            const float sc = dot * SCALE + sh_mask[newpos - s0];
            const float mn   = fmaxf(m, sc);
            const float corr = __expf(m - mn);
            const float p    = __expf(sc - mn);
            l = l * corr + p;
            acc.x = acc.x * corr + p * v4.x;
            acc.y = acc.y * corr + p * v4.y;
            acc.z = acc.z * corr + p * v4.z;
            acc.w = acc.w * corr + p * v4.w;
            m = mn;
        }

        // Merge 8 warps, write split partial.
        if (lane == 0) { sh_m[w] = m; sh_l[w] = l; }
        reinterpret_cast<float4*>(sh_acc[w])[lane] = acc;
        __syncthreads();

        if (tid < D_) {
            float M = sh_m[0];
            #pragma unroll
            for (int i = 1; i < NWARP; i++) M = fmaxf(M, sh_m[i]);
            float od = 0.f, lt = 0.f;
            #pragma unroll
            for (int i = 0; i < NWARP; i++) {
                const float e = __expf(sh_m[i] - M);
                od += e * sh_acc[i][tid];
                lt += e * sh_l[i];
            }
            g_po[(pbase + split) * D_ + tid] = od;
            if (tid == 0) { g_pm[pbase + split] = M; g_pl[pbase + split] = lt; }
        }
        __threadfence();
    }

    if (tid == 0) sh_rank = atomicAdd(&g_cnt[bh], 1u);
    __syncthreads();

    if (sh_rank == NSPLIT - 1) {
        if (tid < D_) {
            float M = -1e30f;
            for (int i = 0; i < nact; i++) M = fmaxf(M, g_pm[pbase + i]);
            float denom = 0.f, od = 0.f;
            for (int i = 0; i < nact; i++) {
                const float e = __expf(g_pm[pbase + i] - M);
                denom += e * g_pl[pbase + i];
                od    += e * g_po[(pbase + i) * D_ + tid];
            }
            out[(size_t)bh * D_ + tid] = od / denom;
        }
        if (tid == 0) g_cnt[bh] = 0;
    }
}

// Inputs (metadata order):
//  0 Q  1 K  2 V  3 Kcache  4 Vcache  5 cos  6 sin  7 mask
//  8 input_length  9 cache_length  10 save_slots  11 fetch_slots  12 max_s
extern "C" void kernel_launch(void* const* d_in, const int* in_sizes, int n_in,
                              void* d_out, int out_size)
{
    const float* Q    = (const float*)d_in[0];
    const float* K    = (const float*)d_in[1];
    const float* V    = (const float*)d_in[2];
    const float* Kc   = (const float*)d_in[3];
    const float* Vc   = (const float*)d_in[4];
    const float* cosT = (const float*)d_in[5];
    const float* sinT = (const float*)d_in[6];
    const float* mask = (const float*)d_in[7];
    const int*   clen = (const int*)d_in[9];
    const int*   fsl  = (const int*)d_in[11];
    float* out = (float*)d_out;

    dim3 grid(NSPLIT, H_, B_);
    paged_attn_fused<<<grid, NTHREAD>>>(Q, K, V, Kc, Vc, cosT, sinT, mask, clen, fsl, out);
}